// round 14
// baseline (speedup 1.0000x reference)
#include <cuda_runtime.h>
#include <cuda_fp16.h>
#include <cstdint>

#define LN_EPS 1e-6f

// Fixed problem shape: M = S*B = 32768, K = H = 1024, N = F = 1024
#define DIM_M 32768
#define DIM_K 1024
#define DIM_N 1024

// Scratch (allocation-free rule: __device__ globals)
__device__ __half g_Ah[(size_t)DIM_M * DIM_K];  // fp16 ln_out (GEMM A, row-major)
__device__ __half g_Bh[(size_t)DIM_K * DIM_N];  // fp16 kernel  (GEMM B, K-major)
__device__ int    g_flagA[256];                 // per-bm-group prep completion (0..8)
__device__ int    g_flagB;                      // B prep completion (0..8)

// ============================================================
// helpers
// ============================================================
__device__ __forceinline__ void cp16(uint32_t smem_dst, const void* g) {
    asm volatile("cp.async.cg.shared.global [%0], [%1], 16;\n" :: "r"(smem_dst), "l"(g));
}
__device__ __forceinline__ void cp_commit() {
    asm volatile("cp.async.commit_group;\n");
}
__device__ __forceinline__ void ldsm4(uint32_t& r0, uint32_t& r1, uint32_t& r2,
                                      uint32_t& r3, uint32_t addr) {
    asm volatile("ldmatrix.sync.aligned.m8n8.x4.shared.b16 {%0,%1,%2,%3}, [%4];"
                 : "=r"(r0), "=r"(r1), "=r"(r2), "=r"(r3) : "r"(addr));
}
__device__ __forceinline__ void ldsm4t(uint32_t& r0, uint32_t& r1, uint32_t& r2,
                                       uint32_t& r3, uint32_t addr) {
    asm volatile("ldmatrix.sync.aligned.m8n8.x4.trans.shared.b16 {%0,%1,%2,%3}, [%4];"
                 : "=r"(r0), "=r"(r1), "=r"(r2), "=r"(r3) : "r"(addr));
}
__device__ __forceinline__ void mma_f16(float* c, const uint32_t* a, const uint32_t* b) {
    asm volatile(
        "mma.sync.aligned.m16n8k16.row.col.f32.f16.f16.f32 "
        "{%0,%1,%2,%3}, {%4,%5,%6,%7}, {%8,%9}, {%0,%1,%2,%3};\n"
        : "+f"(c[0]), "+f"(c[1]), "+f"(c[2]), "+f"(c[3])
        : "r"(a[0]), "r"(a[1]), "r"(a[2]), "r"(a[3]), "r"(b[0]), "r"(b[1]));
}

// ============================================================
// init kernel: reset flags every call (graph replays reuse globals)
// ============================================================
__global__ void init_flags() {
    g_flagA[threadIdx.x] = 0;
    if (threadIdx.x == 0) g_flagB = 0;
}

// ============================================================
// GEMM tiling constants (R12 mainloop, unchanged)
// ============================================================
#define STAGES 3
#define BM 128
#define BN 128
#define BKH 64                              // k-halfs per tile
#define A_ROW_B 144                         // 64 halfs (128B) + 16B pad
#define B_ROW_B 272                         // 128 halfs (256B) + 16B pad
#define TILE_A (BM * A_ROW_B)               // 18432
#define TILE_BB (BKH * B_ROW_B)             // 17408
#define STAGE_B (TILE_A + TILE_BB)          // 35840
#define GEMM_SMEM (STAGES * STAGE_B)        // 107520 -> 2 CTAs/SM

__device__ __forceinline__ void load_stage(uint32_t sb, int slot, int kt,
                                           const __half* Ag, const __half* Bg, int tid) {
    uint32_t st = sb + slot * STAGE_B;
    const int k0 = kt * BKH;
    #pragma unroll
    for (int i = 0; i < 8; i++) {          // A: 128 rows x 8 chunks = 1024 / 128 thr
        int c = i * 128 + tid;
        int r = c >> 3, j = c & 7;
        cp16(st + (uint32_t)(r * A_ROW_B + j * 16),
             Ag + (size_t)r * DIM_K + k0 + j * 8);
    }
    #pragma unroll
    for (int i = 0; i < 8; i++) {          // B: 64 rows x 16 chunks = 1024 / 128 thr
        int c = i * 128 + tid;
        int r = c >> 4, j = c & 15;
        cp16(st + TILE_A + (uint32_t)(r * B_ROW_B + j * 16),
             Bg + (size_t)(k0 + r) * DIM_N + j * 8);
    }
    cp_commit();
}

__device__ __forceinline__ void ldsm_frags(uint32_t awarp, uint32_t bwarp, int kc,
                                           uint32_t a[4][4], uint32_t b[4][4]) {
    #pragma unroll
    for (int mt = 0; mt < 4; mt++)
        ldsm4(a[mt][0], a[mt][1], a[mt][2], a[mt][3],
              awarp + (uint32_t)(mt * 16) * A_ROW_B + kc * 32);
    #pragma unroll
    for (int g = 0; g < 4; g++)            // each x4.trans: 16 n-cols
        ldsm4t(b[g][0], b[g][1], b[g][2], b[g][3],
               bwarp + (uint32_t)(kc * 16) * B_ROW_B + g * 32);
}

// ============================================================
// FUSED kernel: per-CTA prep phase (flag-synced, overlaps with
// other CTAs' mainloops) + R12 FP16 GEMM mainloop.
//   grid (8, 256); bid = bn + 8*bm -> each bm-group is 8
//   consecutive bids (monotone dispatch -> no deadlock: at most
//   one incomplete group can be resident at a time).
// ============================================================
__global__ void __launch_bounds__(128, 2)
fused_ln_gemm(const float* __restrict__ x,
              const float* __restrict__ scale,
              const float* __restrict__ bias,
              const float* __restrict__ B,
              float* __restrict__ C,
              float* __restrict__ ln_out) {
    extern __shared__ __align__(1024) char smem[];
    uint32_t sb;
    asm("{ .reg .u64 t; cvta.to.shared.u64 t, %1; cvt.u32.u64 %0, t; }"
        : "=r"(sb) : "l"(smem));

    const int tid = threadIdx.x;
    const int bm = blockIdx.y, bn = blockIdx.x;

    // ---------- phase 1: prep (this CTA's slice) ----------
    {
        __shared__ float red[2][2][4];  // [row parity][sum|sq][warp]
        const int wid = tid >> 5, lid = tid & 31;
        // this thread owns cols tid*8 .. tid*8+7
        const float4 sc0 = reinterpret_cast<const float4*>(scale)[tid * 2];
        const float4 sc1 = reinterpret_cast<const float4*>(scale)[tid * 2 + 1];
        const float4 bi0 = reinterpret_cast<const float4*>(bias)[tid * 2];
        const float4 bi1 = reinterpret_cast<const float4*>(bias)[tid * 2 + 1];
        const int row0 = bm * BM + bn * 16;
        for (int i = 0; i < 16; i++) {
            const int row = row0 + i;
            const float4* xr = reinterpret_cast<const float4*>(x + (size_t)row * DIM_K);
            float4 v0 = xr[tid * 2], v1 = xr[tid * 2 + 1];
            float s  = v0.x + v0.y + v0.z + v0.w + v1.x + v1.y + v1.z + v1.w;
            float sq = v0.x * v0.x + v0.y * v0.y + v0.z * v0.z + v0.w * v0.w +
                       v1.x * v1.x + v1.y * v1.y + v1.z * v1.z + v1.w * v1.w;
            #pragma unroll
            for (int o = 16; o > 0; o >>= 1) {
                s  += __shfl_xor_sync(0xffffffffu, s,  o);
                sq += __shfl_xor_sync(0xffffffffu, sq, o);
            }
            if (lid == 0) { red[i & 1][0][wid] = s; red[i & 1][1][wid] = sq; }
            __syncthreads();   // one barrier/row; parity buffer avoids WAR
            s  = red[i & 1][0][0] + red[i & 1][0][1] + red[i & 1][0][2] + red[i & 1][0][3];
            sq = red[i & 1][1][0] + red[i & 1][1][1] + red[i & 1][1][2] + red[i & 1][1][3];
            const float invH = 1.0f / (float)DIM_K;
            float mu   = s * invH;
            float var  = sq * invH - mu * mu;
            float rstd = rsqrtf(var + LN_EPS);
            float4 o0, o1;
            o0.x = (v0.x - mu) * rstd * sc0.x + bi0.x;
            o0.y = (v0.y - mu) * rstd * sc0.y + bi0.y;
            o0.z = (v0.z - mu) * rstd * sc0.z + bi0.z;
            o0.w = (v0.w - mu) * rstd * sc0.w + bi0.w;
            o1.x = (v1.x - mu) * rstd * sc1.x + bi1.x;
            o1.y = (v1.y - mu) * rstd * sc1.y + bi1.y;
            o1.z = (v1.z - mu) * rstd * sc1.z + bi1.z;
            o1.w = (v1.w - mu) * rstd * sc1.w + bi1.w;
            float4* lr = reinterpret_cast<float4*>(ln_out + (size_t)row * DIM_K);
            lr[tid * 2]     = o0;
            lr[tid * 2 + 1] = o1;
            __half2 p0 = __floats2half2_rn(o0.x, o0.y);
            __half2 p1 = __floats2half2_rn(o0.z, o0.w);
            __half2 p2 = __floats2half2_rn(o1.x, o1.y);
            __half2 p3 = __floats2half2_rn(o1.z, o1.w);
            uint4 pk;
            pk.x = *reinterpret_cast<uint32_t*>(&p0);
            pk.y = *reinterpret_cast<uint32_t*>(&p1);
            pk.z = *reinterpret_cast<uint32_t*>(&p2);
            pk.w = *reinterpret_cast<uint32_t*>(&p3);
            reinterpret_cast<uint4*>(g_Ah + (size_t)row * DIM_K)[tid] = pk;
        }
    }
    // bm==0 group (bids 0..7, launched first): convert B slice to fp16
    if (bm == 0) {
        const float* Bs = B    + (size_t)bn * 128 * DIM_N;
        __half*      Bd = g_Bh + (size_t)bn * 128 * DIM_N;
        #pragma unroll 4
        for (int i = 0; i < 256; i++) {
            int idx = i * 128 + tid;   // float4 index within the 128x1024 slice
            float4 v = reinterpret_cast<const float4*>(Bs)[idx];
            __half2 p0 = __floats2half2_rn(v.x, v.y);
            __half2 p1 = __floats2half2_rn(v.z, v.w);
            uint2 pk;
            pk.x = *reinterpret_cast<uint32_t*>(&p0);
            pk.y = *reinterpret_cast<uint32_t*>(&p1);
            reinterpret_cast<uint2*>(Bd)[idx] = pk;
        }
    }

    // ---------- flag publish + wait ----------
    __threadfence();        // make this thread's stores device-visible
    __syncthreads();        // all threads' fences done before tid0 publishes
    if (tid == 0) {
        atomicAdd(&g_flagA[bm], 1);
        if (bm == 0) atomicAdd(&g_flagB, 1);
        while (atomicAdd(&g_flagA[bm], 0) < 8) __nanosleep(100);
        while (atomicAdd(&g_flagB, 0) < 8)     __nanosleep(100);
        __threadfence();
    }
    __syncthreads();

    // ---------- phase 2: GEMM mainloop (R12, unchanged) ----------
    const int warp = tid >> 5, lane = tid & 31;
    const int wm = warp >> 1;        // 0..1 -> m offset wm*64
    const int wn = warp & 1;         // 0..1 -> n offset wn*64
    const int gid = lane >> 2;       // 0..7
    const int tig = lane & 3;        // 0..3

    const uint32_t aoff = (uint32_t)((lane & 15) * A_ROW_B + (lane >> 4) * 16) +
                          (uint32_t)(wm * 64) * A_ROW_B;
    const uint32_t boff = (uint32_t)(((lane & 7) + 8 * ((lane >> 3) & 1)) * B_ROW_B +
                                     (lane >> 4) * 16) + (uint32_t)(wn * 128) + TILE_A;

    const __half* Ag = g_Ah + (size_t)bm * BM * DIM_K;
    const __half* Bg = g_Bh + bn * BN;

    float acc[4][8][4];
    #pragma unroll
    for (int i = 0; i < 4; i++)
        #pragma unroll
        for (int j = 0; j < 8; j++)
            #pragma unroll
            for (int r = 0; r < 4; r++) acc[i][j][r] = 0.f;

    const int T = DIM_K / BKH;   // 16
    load_stage(sb, 0, 0, Ag, Bg, tid);
    load_stage(sb, 1, 1, Ag, Bg, tid);

    uint32_t a[2][4][4], b[2][4][4];

    for (int t = 0; t < T; t++) {
        asm volatile("cp.async.wait_group 0;\n");
        __syncthreads();

        const uint32_t as    = sb + (t % 3) * STAGE_B;
        const uint32_t awarp = as + aoff;
        const uint32_t bwarp = as + boff;

        if (t == 0) ldsm_frags(awarp, bwarp, 0, a[0], b[0]);

        #pragma unroll
        for (int kc = 0; kc < 4; kc++) {
            const int cur = kc & 1, nxt = cur ^ 1;
            if (kc == 1) {
                if (t + 2 < T) load_stage(sb, (t + 2) % 3, t + 2, Ag, Bg, tid);
                else           cp_commit();
            }
            if (kc < 3) {
                ldsm_frags(awarp, bwarp, kc + 1, a[nxt], b[nxt]);
            } else if (t + 1 < T) {
                const uint32_t as2 = sb + ((t + 1) % 3) * STAGE_B;
                ldsm_frags(as2 + aoff, as2 + boff, 0, a[nxt], b[nxt]);
            }
            #pragma unroll
            for (int mt = 0; mt < 4; mt++)
                #pragma unroll
                for (int nf = 0; nf < 8; nf++)
                    mma_f16(acc[mt][nf], a[cur][mt], &b[cur][nf >> 1][(nf & 1) * 2]);
        }
    }

    float* Cb = C + (size_t)(bm * BM) * DIM_N + bn * BN;
    #pragma unroll
    for (int mt = 0; mt < 4; mt++) {
        const int m = wm * 64 + mt * 16 + gid;
        #pragma unroll
        for (int nf = 0; nf < 8; nf++) {
            const int n = wn * 64 + nf * 8 + 2 * tig;
            const float* a4 = acc[mt][nf];
            *reinterpret_cast<float2*>(Cb + (size_t)m * DIM_N + n) =
                make_float2(a4[0], a4[1]);
            *reinterpret_cast<float2*>(Cb + (size_t)(m + 8) * DIM_N + n) =
                make_float2(a4[2], a4[3]);
        }
    }
}

// ============================================================
// launch
// ============================================================
extern "C" void kernel_launch(void* const* d_in, const int* in_sizes, int n_in,
                              void* d_out, int out_size) {
    const float* x       = (const float*)d_in[0];  // (S,B,H)
    const float* scale   = (const float*)d_in[1];  // (H,)
    const float* ln_bias = (const float*)d_in[2];  // (H,)
    const float* kern    = (const float*)d_in[3];  // (H,F)

    const int H = in_sizes[1];
    const int M = in_sizes[0] / H;   // 32768
    const int F = in_sizes[3] / H;   // 1024

    float* out    = (float*)d_out;             // (M,F) first
    float* ln_out = out + (size_t)M * F;       // (M,H) second

    init_flags<<<1, 256>>>();

    cudaFuncSetAttribute(fused_ln_gemm,
                         cudaFuncAttributeMaxDynamicSharedMemorySize, GEMM_SMEM);
    fused_ln_gemm<<<dim3(F / BN, M / BM), 128, GEMM_SMEM>>>(
        x, scale, ln_bias, kern, out, ln_out);
}

// round 15
// speedup vs baseline: 1.3002x; 1.3002x over previous
#include <cuda_runtime.h>
#include <cuda_fp16.h>
#include <cstdint>

#define LN_EPS 1e-6f

// Fixed problem shape: M = S*B = 32768, K = H = 1024, N = F = 1024
#define DIM_M 32768
#define DIM_K 1024
#define DIM_N 1024

// Scratch (allocation-free rule: __device__ globals)
__device__ __half g_Ah[(size_t)DIM_M * DIM_K];  // fp16 ln_out (GEMM A, row-major)
__device__ __half g_Bh[(size_t)DIM_K * DIM_N];  // fp16 kernel  (GEMM B, K-major)

// ============================================================
// helpers
// ============================================================
__device__ __forceinline__ void cp16(uint32_t smem_dst, const void* g) {
    asm volatile("cp.async.cg.shared.global [%0], [%1], 16;\n" :: "r"(smem_dst), "l"(g));
}
__device__ __forceinline__ void cp_commit() {
    asm volatile("cp.async.commit_group;\n");
}
__device__ __forceinline__ void ldsm4(uint32_t& r0, uint32_t& r1, uint32_t& r2,
                                      uint32_t& r3, uint32_t addr) {
    asm volatile("ldmatrix.sync.aligned.m8n8.x4.shared.b16 {%0,%1,%2,%3}, [%4];"
                 : "=r"(r0), "=r"(r1), "=r"(r2), "=r"(r3) : "r"(addr));
}
__device__ __forceinline__ void ldsm4t(uint32_t& r0, uint32_t& r1, uint32_t& r2,
                                       uint32_t& r3, uint32_t addr) {
    asm volatile("ldmatrix.sync.aligned.m8n8.x4.trans.shared.b16 {%0,%1,%2,%3}, [%4];"
                 : "=r"(r0), "=r"(r1), "=r"(r2), "=r"(r3) : "r"(addr));
}
__device__ __forceinline__ void mma_f16(float* c, const uint32_t* a, const uint32_t* b) {
    asm volatile(
        "mma.sync.aligned.m16n8k16.row.col.f32.f16.f16.f32 "
        "{%0,%1,%2,%3}, {%4,%5,%6,%7}, {%8,%9}, {%0,%1,%2,%3};\n"
        : "+f"(c[0]), "+f"(c[1]), "+f"(c[2]), "+f"(c[3])
        : "r"(a[0]), "r"(a[1]), "r"(a[2]), "r"(a[3]), "r"(b[0]), "r"(b[1]));
}

// ============================================================
// prep kernel v2: warp-per-row LayerNorm (no block barriers,
// 8 float4 loads in flight per thread for DRAM saturation).
//   blocks [0, M/8)            -> 8 LN rows each (1 warp/row)
//   blocks [M/8, M/8 + 1024)   -> fp16-round weight (elementwise)
// ln_out written exact fp32; fp16 copy of it goes to g_Ah.
// ============================================================
#define LN_BLOCKS (DIM_M / 8)

__global__ void prep_kernel(const float* __restrict__ x,
                            const float* __restrict__ scale,
                            const float* __restrict__ bias,
                            const float* __restrict__ B,
                            float* __restrict__ ln_out) {
    if (blockIdx.x < LN_BLOCKS) {
        const int wid = threadIdx.x >> 5, lane = threadIdx.x & 31;
        const int row = blockIdx.x * 8 + wid;
        const float4* xr = reinterpret_cast<const float4*>(x + (size_t)row * DIM_K);

        float4 v[8];
        #pragma unroll
        for (int i = 0; i < 8; i++) v[i] = xr[lane + 32 * i];

        float s = 0.f, sq = 0.f;
        #pragma unroll
        for (int i = 0; i < 8; i++) {
            s  += v[i].x + v[i].y + v[i].z + v[i].w;
            sq += v[i].x * v[i].x + v[i].y * v[i].y +
                  v[i].z * v[i].z + v[i].w * v[i].w;
        }
        #pragma unroll
        for (int o = 16; o > 0; o >>= 1) {
            s  += __shfl_xor_sync(0xffffffffu, s,  o);
            sq += __shfl_xor_sync(0xffffffffu, sq, o);
        }

        const float invH = 1.0f / (float)DIM_K;
        float mu   = s * invH;
        float var  = sq * invH - mu * mu;
        float rstd = rsqrtf(var + LN_EPS);

        float4* lr = reinterpret_cast<float4*>(ln_out + (size_t)row * DIM_K);
        uint2*  ar = reinterpret_cast<uint2*>(g_Ah + (size_t)row * DIM_K);
        #pragma unroll
        for (int i = 0; i < 8; i++) {
            const int idx = lane + 32 * i;
            float4 sc = reinterpret_cast<const float4*>(scale)[idx];
            float4 bi = reinterpret_cast<const float4*>(bias)[idx];
            float4 o;
            o.x = (v[i].x - mu) * rstd * sc.x + bi.x;
            o.y = (v[i].y - mu) * rstd * sc.y + bi.y;
            o.z = (v[i].z - mu) * rstd * sc.z + bi.z;
            o.w = (v[i].w - mu) * rstd * sc.w + bi.w;
            lr[idx] = o;
            __half2 p0 = __floats2half2_rn(o.x, o.y);
            __half2 p1 = __floats2half2_rn(o.z, o.w);
            uint2 pk;
            pk.x = *reinterpret_cast<uint32_t*>(&p0);
            pk.y = *reinterpret_cast<uint32_t*>(&p1);
            ar[idx] = pk;
        }
    } else {
        // elementwise fp16 round of the weight (keeps K-major layout)
        size_t base = (size_t)(blockIdx.x - LN_BLOCKS) * 1024 + threadIdx.x * 4;
        float4 v = *reinterpret_cast<const float4*>(B + base);
        __half2 p0 = __floats2half2_rn(v.x, v.y);
        __half2 p1 = __floats2half2_rn(v.z, v.w);
        uint2 pk;
        pk.x = *reinterpret_cast<uint32_t*>(&p0);
        pk.y = *reinterpret_cast<uint32_t*>(&p1);
        *reinterpret_cast<uint2*>(g_Bh + base) = pk;
    }
}

// ============================================================
// FP16 GEMM (mma.m16n8k16 + ldmatrix): C[M,N] = g_Ah * g_Bh
// R10 shape (256 threads, 8 warps 2x4, warp tile 64x32, regs=128
// -> 2 CTAs/SM) with a finer/deeper pipeline: BK=32, 5-stage
// cp.async ring, prefetch distance 4, top wait_group 2 (newest
// two loads always in flight). Cross-tile kc0 preload kept.
// ============================================================
#define STAGES 5
#define BM 128
#define BN 128
#define BKH 32                              // k-halfs per tile
#define A_ROW_B 80                          // 32 halfs (64B) + 16B pad
#define B_ROW_B 272                         // 128 halfs (256B) + 16B pad
#define TILE_A (BM * A_ROW_B)               // 10240
#define TILE_BB (BKH * B_ROW_B)             // 8704
#define STAGE_B (TILE_A + TILE_BB)          // 18944
#define GEMM_SMEM (STAGES * STAGE_B)        // 94720 -> 2 CTAs/SM

__device__ __forceinline__ void load_stage(uint32_t sb, int slot, int kt,
                                           const __half* Ag, const __half* Bg, int tid) {
    uint32_t st = sb + slot * STAGE_B;
    const int k0 = kt * BKH;
    #pragma unroll
    for (int i = 0; i < 2; i++) {          // A: 128 rows x 4 chunks = 512 / 256 thr
        int c = i * 256 + tid;
        int r = c >> 2, j = c & 3;
        cp16(st + (uint32_t)(r * A_ROW_B + j * 16),
             Ag + (size_t)r * DIM_K + k0 + j * 8);
    }
    #pragma unroll
    for (int i = 0; i < 2; i++) {          // B: 32 rows x 16 chunks = 512 / 256 thr
        int c = i * 256 + tid;
        int r = c >> 4, j = c & 15;
        cp16(st + TILE_A + (uint32_t)(r * B_ROW_B + j * 16),
             Bg + (size_t)(k0 + r) * DIM_N + j * 8);
    }
    cp_commit();
}

__device__ __forceinline__ void ldsm_frags(uint32_t awarp, uint32_t bwarp, int kc,
                                           uint32_t a[4][4], uint32_t b[2][4]) {
    #pragma unroll
    for (int mt = 0; mt < 4; mt++)
        ldsm4(a[mt][0], a[mt][1], a[mt][2], a[mt][3],
              awarp + (uint32_t)(mt * 16) * A_ROW_B + kc * 32);
    #pragma unroll
    for (int g = 0; g < 2; g++)            // each x4.trans: 16 n-cols
        ldsm4t(b[g][0], b[g][1], b[g][2], b[g][3],
               bwarp + (uint32_t)(kc * 16) * B_ROW_B + g * 32);
}

__global__ void __launch_bounds__(256, 2)
gemm_f16(float* __restrict__ C) {
    extern __shared__ __align__(1024) char smem[];
    uint32_t sb;
    asm("{ .reg .u64 t; cvta.to.shared.u64 t, %1; cvt.u32.u64 %0, t; }"
        : "=r"(sb) : "l"(smem));

    const int tid  = threadIdx.x;
    const int warp = tid >> 5, lane = tid & 31;
    const int wm = warp >> 2;        // 0..1 -> m offset wm*64
    const int wn = warp & 3;         // 0..3 -> n offset wn*32
    const int gid = lane >> 2;       // 0..7
    const int tig = lane & 3;        // 0..3

    // A (non-trans x4): rows l&15, col-group (l>>4)*16B
    const uint32_t aoff = (uint32_t)((lane & 15) * A_ROW_B + (lane >> 4) * 16) +
                          (uint32_t)(wm * 64) * A_ROW_B;
    // B (trans x4): k-rows (l&7)+8*((l>>3)&1), n-group (l>>4)*16B; warp n = wn*32 halfs
    const uint32_t boff = (uint32_t)(((lane & 7) + 8 * ((lane >> 3) & 1)) * B_ROW_B +
                                     (lane >> 4) * 16) + (uint32_t)(wn * 64) + TILE_A;

    const int bm = blockIdx.y, bn = blockIdx.x;
    const __half* Ag = g_Ah + (size_t)bm * BM * DIM_K;
    const __half* Bg = g_Bh + bn * BN;

    float acc[4][4][4];   // [mt][nf][reg]
    #pragma unroll
    for (int i = 0; i < 4; i++)
        #pragma unroll
        for (int j = 0; j < 4; j++)
            #pragma unroll
            for (int r = 0; r < 4; r++) acc[i][j][r] = 0.f;

    const int T = DIM_K / BKH;   // 32
    load_stage(sb, 0, 0, Ag, Bg, tid);
    load_stage(sb, 1, 1, Ag, Bg, tid);
    load_stage(sb, 2, 2, Ag, Bg, tid);
    load_stage(sb, 3, 3, Ag, Bg, tid);

    // fragment buffers persist ACROSS tiles (cross-tile rolling pipeline)
    uint32_t a[2][4][4], b[2][2][4];

    for (int t = 0; t < T; t++) {
        // pending <= {t+1, t+2, t+3}; wait_group 2 completes through t+1
        // (t+1 is what the cross-tile preload reads), keeps the two
        // newest loads in flight.
        asm volatile("cp.async.wait_group 2;\n");
        __syncthreads();

        const uint32_t as    = sb + (t % 5) * STAGE_B;
        const uint32_t awarp = as + aoff;
        const uint32_t bwarp = as + boff;

        if (t == 0) ldsm_frags(awarp, bwarp, 0, a[0], b[0]);  // prologue only

        #pragma unroll
        for (int kc = 0; kc < 2; kc++) {
            const int cur = kc & 1, nxt = cur ^ 1;
            if (kc == 0) {
                // preload kc1 frags, then refill tile t+4 into slot
                // (t+4)%5 (= slot of tile t-1; all warps finished t-1
                // before this iteration's barrier).
                ldsm_frags(awarp, bwarp, 1, a[nxt], b[nxt]);
                if (t + 4 < T) load_stage(sb, (t + 4) % 5, t + 4, Ag, Bg, tid);
                else           cp_commit();
            } else if (t + 1 < T) {
                // preload NEXT tile's kc0 from slot (t+1)%5 (completed by
                // this iteration's wait_group 2 + barrier; refill targets
                // (t+4)%5, disjoint). Buffer parity self-aligns.
                const uint32_t as2 = sb + ((t + 1) % 5) * STAGE_B;
                ldsm_frags(as2 + aoff, as2 + boff, 0, a[nxt], b[nxt]);
            }
            #pragma unroll
            for (int mt = 0; mt < 4; mt++)
                #pragma unroll
                for (int nf = 0; nf < 4; nf++)
                    mma_f16(acc[mt][nf], a[cur][mt], &b[cur][nf >> 1][(nf & 1) * 2]);
        }
        // no trailing barrier: next iteration's wait+sync covers the hazard.
    }

    // epilogue: direct float2 stores
    float* Cb = C + (size_t)(bm * BM) * DIM_N + bn * BN;
    #pragma unroll
    for (int mt = 0; mt < 4; mt++) {
        const int m = wm * 64 + mt * 16 + gid;
        #pragma unroll
        for (int nf = 0; nf < 4; nf++) {
            const int n = wn * 32 + nf * 8 + 2 * tig;
            const float* a4 = acc[mt][nf];
            *reinterpret_cast<float2*>(Cb + (size_t)m * DIM_N + n) =
                make_float2(a4[0], a4[1]);
            *reinterpret_cast<float2*>(Cb + (size_t)(m + 8) * DIM_N + n) =
                make_float2(a4[2], a4[3]);
        }
    }
}

// ============================================================
// launch
// ============================================================
extern "C" void kernel_launch(void* const* d_in, const int* in_sizes, int n_in,
                              void* d_out, int out_size) {
    const float* x       = (const float*)d_in[0];  // (S,B,H)
    const float* scale   = (const float*)d_in[1];  // (H,)
    const float* ln_bias = (const float*)d_in[2];  // (H,)
    const float* kern    = (const float*)d_in[3];  // (H,F)

    const int H = in_sizes[1];
    const int M = in_sizes[0] / H;   // 32768
    const int F = in_sizes[3] / H;   // 1024

    float* out    = (float*)d_out;             // (M,F) first
    float* ln_out = out + (size_t)M * F;       // (M,H) second

    prep_kernel<<<LN_BLOCKS + (H * F) / 1024, 256>>>(x, scale, ln_bias, kern, ln_out);

    cudaFuncSetAttribute(gemm_f16, cudaFuncAttributeMaxDynamicSharedMemorySize, GEMM_SMEM);
    gemm_f16<<<dim3(F / BN, M / BM), 256, GEMM_SMEM>>>(out);
}

// round 16
// speedup vs baseline: 1.5160x; 1.1660x over previous
#include <cuda_runtime.h>
#include <cuda_fp16.h>
#include <cstdint>

#define LN_EPS 1e-6f

// Fixed problem shape: M = S*B = 32768, K = H = 1024, N = F = 1024
#define DIM_M 32768
#define DIM_K 1024
#define DIM_N 1024

// Scratch (allocation-free rule: __device__ globals)
__device__ __half g_Ah[(size_t)DIM_M * DIM_K];  // fp16 ln_out (GEMM A, row-major)
__device__ __half g_Bh[(size_t)DIM_K * DIM_N];  // fp16 kernel  (GEMM B, K-major)

// ============================================================
// helpers
// ============================================================
__device__ __forceinline__ void cp16(uint32_t smem_dst, const void* g) {
    asm volatile("cp.async.cg.shared.global [%0], [%1], 16;\n" :: "r"(smem_dst), "l"(g));
}
__device__ __forceinline__ void cp_commit() {
    asm volatile("cp.async.commit_group;\n");
}
__device__ __forceinline__ void ldsm4(uint32_t& r0, uint32_t& r1, uint32_t& r2,
                                      uint32_t& r3, uint32_t addr) {
    asm volatile("ldmatrix.sync.aligned.m8n8.x4.shared.b16 {%0,%1,%2,%3}, [%4];"
                 : "=r"(r0), "=r"(r1), "=r"(r2), "=r"(r3) : "r"(addr));
}
__device__ __forceinline__ void ldsm4t(uint32_t& r0, uint32_t& r1, uint32_t& r2,
                                       uint32_t& r3, uint32_t addr) {
    asm volatile("ldmatrix.sync.aligned.m8n8.x4.trans.shared.b16 {%0,%1,%2,%3}, [%4];"
                 : "=r"(r0), "=r"(r1), "=r"(r2), "=r"(r3) : "r"(addr));
}
__device__ __forceinline__ void mma_f16(float* c, const uint32_t* a, const uint32_t* b) {
    asm volatile(
        "mma.sync.aligned.m16n8k16.row.col.f32.f16.f16.f32 "
        "{%0,%1,%2,%3}, {%4,%5,%6,%7}, {%8,%9}, {%0,%1,%2,%3};\n"
        : "+f"(c[0]), "+f"(c[1]), "+f"(c[2]), "+f"(c[3])
        : "r"(a[0]), "r"(a[1]), "r"(a[2]), "r"(a[3]), "r"(b[0]), "r"(b[1]));
}

// ============================================================
// prep kernel (R15 version, measured 50.7us): warp-per-row LN,
// no block barriers, 8 float4 loads in flight per thread.
//   blocks [0, M/8)            -> 8 LN rows each (1 warp/row)
//   blocks [M/8, M/8 + 1024)   -> fp16-round weight (elementwise)
// ln_out written exact fp32; fp16 copy of it goes to g_Ah.
// ============================================================
#define LN_BLOCKS (DIM_M / 8)

__global__ void prep_kernel(const float* __restrict__ x,
                            const float* __restrict__ scale,
                            const float* __restrict__ bias,
                            const float* __restrict__ B,
                            float* __restrict__ ln_out) {
    if (blockIdx.x < LN_BLOCKS) {
        const int wid = threadIdx.x >> 5, lane = threadIdx.x & 31;
        const int row = blockIdx.x * 8 + wid;
        const float4* xr = reinterpret_cast<const float4*>(x + (size_t)row * DIM_K);

        float4 v[8];
        #pragma unroll
        for (int i = 0; i < 8; i++) v[i] = xr[lane + 32 * i];

        float s = 0.f, sq = 0.f;
        #pragma unroll
        for (int i = 0; i < 8; i++) {
            s  += v[i].x + v[i].y + v[i].z + v[i].w;
            sq += v[i].x * v[i].x + v[i].y * v[i].y +
                  v[i].z * v[i].z + v[i].w * v[i].w;
        }
        #pragma unroll
        for (int o = 16; o > 0; o >>= 1) {
            s  += __shfl_xor_sync(0xffffffffu, s,  o);
            sq += __shfl_xor_sync(0xffffffffu, sq, o);
        }

        const float invH = 1.0f / (float)DIM_K;
        float mu   = s * invH;
        float var  = sq * invH - mu * mu;
        float rstd = rsqrtf(var + LN_EPS);

        float4* lr = reinterpret_cast<float4*>(ln_out + (size_t)row * DIM_K);
        uint2*  ar = reinterpret_cast<uint2*>(g_Ah + (size_t)row * DIM_K);
        #pragma unroll
        for (int i = 0; i < 8; i++) {
            const int idx = lane + 32 * i;
            float4 sc = reinterpret_cast<const float4*>(scale)[idx];
            float4 bi = reinterpret_cast<const float4*>(bias)[idx];
            float4 o;
            o.x = (v[i].x - mu) * rstd * sc.x + bi.x;
            o.y = (v[i].y - mu) * rstd * sc.y + bi.y;
            o.z = (v[i].z - mu) * rstd * sc.z + bi.z;
            o.w = (v[i].w - mu) * rstd * sc.w + bi.w;
            lr[idx] = o;
            __half2 p0 = __floats2half2_rn(o.x, o.y);
            __half2 p1 = __floats2half2_rn(o.z, o.w);
            uint2 pk;
            pk.x = *reinterpret_cast<uint32_t*>(&p0);
            pk.y = *reinterpret_cast<uint32_t*>(&p1);
            ar[idx] = pk;
        }
    } else {
        // elementwise fp16 round of the weight (keeps K-major layout)
        size_t base = (size_t)(blockIdx.x - LN_BLOCKS) * 1024 + threadIdx.x * 4;
        float4 v = *reinterpret_cast<const float4*>(B + base);
        __half2 p0 = __floats2half2_rn(v.x, v.y);
        __half2 p1 = __floats2half2_rn(v.z, v.w);
        uint2 pk;
        pk.x = *reinterpret_cast<uint32_t*>(&p0);
        pk.y = *reinterpret_cast<uint32_t*>(&p1);
        *reinterpret_cast<uint2*>(g_Bh + base) = pk;
    }
}

// ============================================================
// FP16 GEMM — EXACT R10 configuration (measured 173.4us):
// BM=BN=128, BK=64 halfs; 256 threads (8 warps 2x4), warp tile
// 64x32; 3-stage cp.async ring, 2 CTAs/SM, one barrier per tile.
// Cross-tile kc0 fragment preload; refill burst at kc==1.
// ============================================================
#define STAGES 3
#define BM 128
#define BN 128
#define BKH 64                              // k-halfs per tile
#define A_ROW_B 144                         // 64 halfs (128B) + 16B pad
#define B_ROW_B 272                         // 128 halfs (256B) + 16B pad
#define TILE_A (BM * A_ROW_B)               // 18432
#define TILE_BB (BKH * B_ROW_B)             // 17408
#define STAGE_B (TILE_A + TILE_BB)          // 35840
#define GEMM_SMEM (STAGES * STAGE_B)        // 107520 -> 2 CTAs/SM

__device__ __forceinline__ void load_stage(uint32_t sb, int slot, int kt,
                                           const __half* Ag, const __half* Bg, int tid) {
    uint32_t st = sb + slot * STAGE_B;
    const int k0 = kt * BKH;
    #pragma unroll
    for (int i = 0; i < 4; i++) {          // A: 128 rows x 8 chunks = 1024 / 256 thr
        int c = i * 256 + tid;
        int r = c >> 3, j = c & 7;
        cp16(st + (uint32_t)(r * A_ROW_B + j * 16),
             Ag + (size_t)r * DIM_K + k0 + j * 8);
    }
    #pragma unroll
    for (int i = 0; i < 4; i++) {          // B: 64 rows x 16 chunks = 1024 / 256 thr
        int c = i * 256 + tid;
        int r = c >> 4, j = c & 15;
        cp16(st + TILE_A + (uint32_t)(r * B_ROW_B + j * 16),
             Bg + (size_t)(k0 + r) * DIM_N + j * 8);
    }
    cp_commit();
}

__device__ __forceinline__ void ldsm_frags(uint32_t awarp, uint32_t bwarp, int kc,
                                           uint32_t a[4][4], uint32_t b[2][4]) {
    #pragma unroll
    for (int mt = 0; mt < 4; mt++)
        ldsm4(a[mt][0], a[mt][1], a[mt][2], a[mt][3],
              awarp + (uint32_t)(mt * 16) * A_ROW_B + kc * 32);
    #pragma unroll
    for (int g = 0; g < 2; g++)            // each x4.trans: 16 n-cols (2 fragments)
        ldsm4t(b[g][0], b[g][1], b[g][2], b[g][3],
               bwarp + (uint32_t)(kc * 16) * B_ROW_B + g * 32);
}

__global__ void __launch_bounds__(256, 2)
gemm_f16(float* __restrict__ C) {
    extern __shared__ __align__(1024) char smem[];
    uint32_t sb;
    asm("{ .reg .u64 t; cvta.to.shared.u64 t, %1; cvt.u32.u64 %0, t; }"
        : "=r"(sb) : "l"(smem));

    const int tid  = threadIdx.x;
    const int warp = tid >> 5, lane = tid & 31;
    const int wm = warp >> 2;        // 0..1 -> m offset wm*64
    const int wn = warp & 3;         // 0..3 -> n offset wn*32
    const int gid = lane >> 2;       // 0..7
    const int tig = lane & 3;        // 0..3

    // A (non-trans x4): rows l&15, col-group (l>>4)*16B
    const uint32_t aoff = (uint32_t)((lane & 15) * A_ROW_B + (lane >> 4) * 16) +
                          (uint32_t)(wm * 64) * A_ROW_B;
    // B (trans x4): k-rows (l&7)+8*((l>>3)&1), n-group (l>>4)*16B; warp n = wn*32 halfs
    const uint32_t boff = (uint32_t)(((lane & 7) + 8 * ((lane >> 3) & 1)) * B_ROW_B +
                                     (lane >> 4) * 16) + (uint32_t)(wn * 64) + TILE_A;

    const int bm = blockIdx.y, bn = blockIdx.x;
    const __half* Ag = g_Ah + (size_t)bm * BM * DIM_K;
    const __half* Bg = g_Bh + bn * BN;

    float acc[4][4][4];   // [mt][nf][reg]
    #pragma unroll
    for (int i = 0; i < 4; i++)
        #pragma unroll
        for (int j = 0; j < 4; j++)
            #pragma unroll
            for (int r = 0; r < 4; r++) acc[i][j][r] = 0.f;

    const int T = DIM_K / BKH;   // 16
    load_stage(sb, 0, 0, Ag, Bg, tid);
    load_stage(sb, 1, 1, Ag, Bg, tid);

    // fragment buffers persist ACROSS tiles (cross-tile rolling pipeline)
    uint32_t a[2][4][4], b[2][2][4];

    for (int t = 0; t < T; t++) {
        // pending = {t, t+1}; wait_group 0 completes both (t+1 is what the
        // cross-tile preload reads; it was issued a full tile ago).
        asm volatile("cp.async.wait_group 0;\n");
        __syncthreads();

        const uint32_t as    = sb + (t % 3) * STAGE_B;
        const uint32_t awarp = as + aoff;
        const uint32_t bwarp = as + boff;

        if (t == 0) ldsm_frags(awarp, bwarp, 0, a[0], b[0]);  // prologue only

        #pragma unroll
        for (int kc = 0; kc < 4; kc++) {
            const int cur = kc & 1, nxt = cur ^ 1;
            if (kc == 1) {
                // refill burst: kc0's HMMAs already queued hide the LDGSTS
                // issue. Slot (t+2)%3 held tile t-1 (all warps done with it
                // before this iteration's barrier).
                if (t + 2 < T) load_stage(sb, (t + 2) % 3, t + 2, Ag, Bg, tid);
                else           cp_commit();
            }
            if (kc < 3) {
                ldsm_frags(awarp, bwarp, kc + 1, a[nxt], b[nxt]);
            } else if (t + 1 < T) {
                // preload NEXT tile's kc0 from slot (t+1)%3 (visible since
                // this iteration's wait 0 + barrier; refill targets
                // (t+2)%3, disjoint). Buffer parity self-aligns.
                const uint32_t as2 = sb + ((t + 1) % 3) * STAGE_B;
                ldsm_frags(as2 + aoff, as2 + boff, 0, a[nxt], b[nxt]);
            }
            #pragma unroll
            for (int mt = 0; mt < 4; mt++)
                #pragma unroll
                for (int nf = 0; nf < 4; nf++)
                    mma_f16(acc[mt][nf], a[cur][mt], &b[cur][nf >> 1][(nf & 1) * 2]);
        }
        // no trailing barrier: next iteration's wait+sync covers the hazard.
    }

    // epilogue: direct float2 stores
    float* Cb = C + (size_t)(bm * BM) * DIM_N + bn * BN;
    #pragma unroll
    for (int mt = 0; mt < 4; mt++) {
        const int m = wm * 64 + mt * 16 + gid;
        #pragma unroll
        for (int nf = 0; nf < 4; nf++) {
            const int n = wn * 32 + nf * 8 + 2 * tig;
            const float* a4 = acc[mt][nf];
            *reinterpret_cast<float2*>(Cb + (size_t)m * DIM_N + n) =
                make_float2(a4[0], a4[1]);
            *reinterpret_cast<float2*>(Cb + (size_t)(m + 8) * DIM_N + n) =
                make_float2(a4[2], a4[3]);
        }
    }
}

// ============================================================
// launch
// ============================================================
extern "C" void kernel_launch(void* const* d_in, const int* in_sizes, int n_in,
                              void* d_out, int out_size) {
    const float* x       = (const float*)d_in[0];  // (S,B,H)
    const float* scale   = (const float*)d_in[1];  // (H,)
    const float* ln_bias = (const float*)d_in[2];  // (H,)
    const float* kern    = (const float*)d_in[3];  // (H,F)

    const int H = in_sizes[1];
    const int M = in_sizes[0] / H;   // 32768
    const int F = in_sizes[3] / H;   // 1024

    float* out    = (float*)d_out;             // (M,F) first
    float* ln_out = out + (size_t)M * F;       // (M,H) second

    prep_kernel<<<LN_BLOCKS + (H * F) / 1024, 256>>>(x, scale, ln_bias, kern, ln_out);

    cudaFuncSetAttribute(gemm_f16, cudaFuncAttributeMaxDynamicSharedMemorySize, GEMM_SMEM);
    gemm_f16<<<dim3(F / BN, M / BM), 256, GEMM_SMEM>>>(out);
}